// round 2
// baseline (speedup 1.0000x reference)
#include <cuda_runtime.h>
#include <cstdint>
#include <cstddef>

#define NB 4
#define INCH 64
#define OC 32
#define V1 40962
#define V2 163842
#define EPSF 1e-5f
#define SLOPE 0.2f

// ---------------- scratch (static device globals; no allocation allowed) ----------------
__device__ float g_x1t[(size_t)NB * V1 * 64];   // x1 transposed to (B, V1, 64)   ~42 MB
__device__ float g_y  [(size_t)NB * V2 * 64];   // upconv + skip concat (B,V2,64) ~168 MB
__device__ float g_h1 [(size_t)NB * V2 * 32];   // conv1 pre-BN                    ~84 MB
__device__ float g_h2 [(size_t)NB * V2 * 32];   // conv2 pre-BN                    ~84 MB
__device__ float g_bn1[NB * 32 * 2];            // (scale, shift) per (b, c)
__device__ float g_bn2[NB * 32 * 2];

extern __shared__ float smem[];

// ---------------- kernel 1: transpose x1 (B,64,V1) -> (B,V1,64) ----------------
__global__ __launch_bounds__(256) void k_xt(const float* __restrict__ x1)
{
    __shared__ float tile[64 * 33];
    int b = blockIdx.y;
    int v0 = blockIdx.x * 32;
    const float* src = x1 + (size_t)b * INCH * V1;
    float* dst = g_x1t + (size_t)b * V1 * 64;
    int tid = threadIdx.x;
    // phase 1: coalesced read over vertices
    for (int idx = tid; idx < 64 * 32; idx += 256) {
        int vl = idx & 31;
        int c = idx >> 5;
        int v = v0 + vl;
        tile[c * 33 + vl] = (v < V1) ? src[(size_t)c * V1 + v] : 0.f;
    }
    __syncthreads();
    // phase 2: coalesced write over channels
    for (int idx = tid; idx < 64 * 32; idx += 256) {
        int c = idx & 63;
        int vl = idx >> 6;
        int v = v0 + vl;
        if (v < V1) dst[(size_t)v * 64 + c] = tile[c * 33 + vl];
    }
}

// ---------------- kernel 2: upconv + scatter + skip concat ----------------
// y[b,v,0:32]  = upconv result, y[b,v,32:64] = x2[b,:,v]
#define UP_WARPS 8
#define UP_VPW 16
#define UP_VPB (UP_WARPS * UP_VPW)   // 128 vertices / block

__global__ __launch_bounds__(256) void k_upconv(const float* __restrict__ x2,
                                                const int* __restrict__ top,
                                                const int* __restrict__ down,
                                                const float* __restrict__ W_up,
                                                const float* __restrict__ b_up)
{
    float* Wt = smem;               // [64][225] transposed W_up, padded
    float* bs = smem + 64 * 225;    // [224]
    int tid = threadIdx.x;
    int b = blockIdx.y;
    int v0 = blockIdx.x * UP_VPB;

    for (int idx = tid; idx < 224 * 64; idx += 256) {
        int r = idx >> 6;           // W_up row (0..223)
        int k = idx & 63;           // in-channel
        Wt[k * 225 + r] = W_up[idx];
    }
    for (int idx = tid; idx < 224; idx += 256) bs[idx] = b_up[idx];
    __syncthreads();

    int warp = tid >> 5, lane = tid & 31;
    const float* x1b = g_x1t + (size_t)b * V1 * 64;
    float* yb = g_y + (size_t)b * V2 * 64;

    for (int g = 0; g < UP_VPW; ++g) {
        int v = v0 + warp * UP_VPW + g;
        if (v >= V2) break;
        if (v < V1) {
            int t = top[v];
            int sv = t / 7, j = t % 7;
            float xr0 = x1b[(size_t)sv * 64 + lane];
            float xr1 = x1b[(size_t)sv * 64 + 32 + lane];
            int wr = j * 32 + lane;
            float acc = bs[wr];
#pragma unroll
            for (int k = 0; k < 32; ++k)
                acc = fmaf(__shfl_sync(0xffffffffu, xr0, k), Wt[k * 225 + wr], acc);
#pragma unroll
            for (int k = 0; k < 32; ++k)
                acc = fmaf(__shfl_sync(0xffffffffu, xr1, k), Wt[(k + 32) * 225 + wr], acc);
            yb[(size_t)v * 64 + lane] = acc;
        } else {
            int n = v - V1;
            int d0 = down[2 * n], d1 = down[2 * n + 1];
            int half = lane >> 4;
            int d = half ? d1 : d0;
            int sv = d / 7, j = d % 7;
            int col0 = (2 * lane) & 31;
            int lq = lane & 15;
            // half-warp cooperative load of the 64-channel source column
            float xr[4];
#pragma unroll
            for (int q = 0; q < 4; ++q)
                xr[q] = x1b[(size_t)sv * 64 + q * 16 + lq];
            int w0 = j * 32 + col0;
            float a0 = bs[w0], a1 = bs[w0 + 1];
            int srcbase = half << 4;
#pragma unroll
            for (int k = 0; k < 64; ++k) {
                float xa = __shfl_sync(0xffffffffu, xr[k >> 4], srcbase + (k & 15));
                a0 = fmaf(xa, Wt[k * 225 + w0], a0);
                a1 = fmaf(xa, Wt[k * 225 + w0 + 1], a1);
            }
            yb[(size_t)v * 64 + lane] = 0.5f * (a0 + a1);
        }
    }

    // skip concat: y[:,32:64] = x2^T (strided read, coalesced write)
    const float* x2b = x2 + (size_t)b * OC * V2;
    for (int idx = tid; idx < UP_VPB * 32; idx += 256) {
        int c = idx & 31, vi = idx >> 5;
        int v = v0 + vi;
        if (v < V2) yb[(size_t)v * 64 + 32 + c] = x2b[(size_t)c * V2 + v];
    }
}

// ---------------- kernel 3: conv1 (gather 7x64 -> GEMM 448x32) ----------------
#define C1_WARPS 8
#define C1_VG 4                      // 4 groups of 4 vertices per warp
#define C1_VPB (C1_WARPS * C1_VG * 4)  // 128 vertices / block
#define WPAD 33

__global__ __launch_bounds__(256) void k_conv1(const int* __restrict__ neigh,
                                               const float* __restrict__ W1,
                                               const float* __restrict__ b1)
{
    float* Wt = smem;                       // [448][33]
    float* ms = smem + 448 * WPAD;          // 8 warps x [448][4]
    int tid = threadIdx.x;
    int b = blockIdx.y;
    int v0 = blockIdx.x * C1_VPB;

    for (int idx = tid; idx < 32 * 448; idx += 256) {
        int c = idx / 448, k = idx % 448;
        Wt[k * WPAD + c] = W1[idx];
    }
    __syncthreads();

    int warp = tid >> 5, lane = tid & 31;
    float* msw = ms + warp * 448 * 4;
    const float* yb = g_y + (size_t)b * V2 * 64;
    float* hb = g_h1 + (size_t)b * V2 * 32;
    float bias = b1[lane];

    for (int g = 0; g < C1_VG; ++g) {
        int vb = v0 + warp * (C1_VG * 4) + g * 4;
#pragma unroll
        for (int vi = 0; vi < 4; ++vi) {
            int v = vb + vi;
            if (v >= V2) break;
            const int* np = neigh + (size_t)v * 7;
#pragma unroll
            for (int k7 = 0; k7 < 7; ++k7) {
                int nb = np[k7];
                const float* src = yb + (size_t)nb * 64;
                msw[(k7 * 64 + lane) * 4 + vi] = src[lane];
                msw[(k7 * 64 + 32 + lane) * 4 + vi] = src[lane + 32];
            }
        }
        __syncwarp();
        float acc0 = bias, acc1 = bias, acc2 = bias, acc3 = bias;
#pragma unroll 8
        for (int k = 0; k < 448; ++k) {
            float w = Wt[k * WPAD + lane];
            float4 m = *(const float4*)(msw + k * 4);
            acc0 = fmaf(m.x, w, acc0);
            acc1 = fmaf(m.y, w, acc1);
            acc2 = fmaf(m.z, w, acc2);
            acc3 = fmaf(m.w, w, acc3);
        }
        __syncwarp();
        if (vb + 0 < V2) hb[(size_t)(vb + 0) * 32 + lane] = acc0;
        if (vb + 1 < V2) hb[(size_t)(vb + 1) * 32 + lane] = acc1;
        if (vb + 2 < V2) hb[(size_t)(vb + 2) * 32 + lane] = acc2;
        if (vb + 3 < V2) hb[(size_t)(vb + 3) * 32 + lane] = acc3;
    }
}

// ---------------- kernel 4/6: BN stats (deterministic, per (b, channel)) ----------------
__global__ __launch_bounds__(256) void k_stats(int which,
                                               const float* __restrict__ gmm,
                                               const float* __restrict__ beta)
{
    const float* hraw = which ? g_h2 : g_h1;
    float* bn = which ? g_bn2 : g_bn1;
    int c = blockIdx.x, b = blockIdx.y;
    const float* p = hraw + (size_t)b * V2 * 32 + c;
    double s = 0.0, s2 = 0.0;
    for (int v = threadIdx.x; v < V2; v += 256) {
        float x = p[(size_t)v * 32];
        s += (double)x;
        s2 += (double)x * (double)x;
    }
    __shared__ double rs[256], rq[256];
    rs[threadIdx.x] = s; rq[threadIdx.x] = s2;
    __syncthreads();
    for (int off = 128; off > 0; off >>= 1) {
        if (threadIdx.x < off) {
            rs[threadIdx.x] += rs[threadIdx.x + off];
            rq[threadIdx.x] += rq[threadIdx.x + off];
        }
        __syncthreads();
    }
    if (threadIdx.x == 0) {
        double mean = rs[0] / (double)V2;
        double var = rq[0] / (double)V2 - mean * mean;
        float scale = gmm[c] * rsqrtf((float)var + EPSF);
        float shift = beta[c] - (float)mean * scale;
        bn[(b * 32 + c) * 2 + 0] = scale;
        bn[(b * 32 + c) * 2 + 1] = shift;
    }
}

// ---------------- kernel 5: conv2 (BN1+LReLU folded into gather) ----------------
__global__ __launch_bounds__(256) void k_conv2(const int* __restrict__ neigh,
                                               const float* __restrict__ W2,
                                               const float* __restrict__ b2)
{
    float* Wt = smem;                       // [224][33]
    float* ms = smem + 224 * WPAD;          // 8 warps x [224][4]
    int tid = threadIdx.x;
    int b = blockIdx.y;
    int v0 = blockIdx.x * C1_VPB;

    for (int idx = tid; idx < 32 * 224; idx += 256) {
        int c = idx / 224, k = idx % 224;
        Wt[k * WPAD + c] = W2[idx];
    }
    __syncthreads();

    int warp = tid >> 5, lane = tid & 31;
    float* msw = ms + warp * 224 * 4;
    const float* hb1 = g_h1 + (size_t)b * V2 * 32;
    float* hb2 = g_h2 + (size_t)b * V2 * 32;
    float bias = b2[lane];
    float sc = g_bn1[(b * 32 + lane) * 2 + 0];
    float sh = g_bn1[(b * 32 + lane) * 2 + 1];

    for (int g = 0; g < C1_VG; ++g) {
        int vb = v0 + warp * (C1_VG * 4) + g * 4;
#pragma unroll
        for (int vi = 0; vi < 4; ++vi) {
            int v = vb + vi;
            if (v >= V2) break;
            const int* np = neigh + (size_t)v * 7;
#pragma unroll
            for (int k7 = 0; k7 < 7; ++k7) {
                int nb = np[k7];
                float val = hb1[(size_t)nb * 32 + lane];
                val = fmaf(val, sc, sh);
                val = (val >= 0.f) ? val : SLOPE * val;
                msw[(k7 * 32 + lane) * 4 + vi] = val;
            }
        }
        __syncwarp();
        float acc0 = bias, acc1 = bias, acc2 = bias, acc3 = bias;
#pragma unroll 8
        for (int k = 0; k < 224; ++k) {
            float w = Wt[k * WPAD + lane];
            float4 m = *(const float4*)(msw + k * 4);
            acc0 = fmaf(m.x, w, acc0);
            acc1 = fmaf(m.y, w, acc1);
            acc2 = fmaf(m.z, w, acc2);
            acc3 = fmaf(m.w, w, acc3);
        }
        __syncwarp();
        if (vb + 0 < V2) hb2[(size_t)(vb + 0) * 32 + lane] = acc0;
        if (vb + 1 < V2) hb2[(size_t)(vb + 1) * 32 + lane] = acc1;
        if (vb + 2 < V2) hb2[(size_t)(vb + 2) * 32 + lane] = acc2;
        if (vb + 3 < V2) hb2[(size_t)(vb + 3) * 32 + lane] = acc3;
    }
}

// ---------------- kernel 7: BN2 + LReLU + transpose to (B,32,V2) ----------------
__global__ __launch_bounds__(256) void k_final(float* __restrict__ out)
{
    __shared__ float tile[32 * 33];
    int b = blockIdx.y;
    int v0 = blockIdx.x * 32;
    const float* hb = g_h2 + (size_t)b * V2 * 32;
    int tid = threadIdx.x;
    for (int idx = tid; idx < 1024; idx += 256) {
        int c = idx & 31, vi = idx >> 5;
        int v = v0 + vi;
        tile[vi * 33 + c] = (v < V2) ? hb[(size_t)v * 32 + c] : 0.f;
    }
    __syncthreads();
    for (int idx = tid; idx < 1024; idx += 256) {
        int vi = idx & 31, c = idx >> 5;
        int v = v0 + vi;
        if (v < V2) {
            float scv = g_bn2[(b * 32 + c) * 2 + 0];
            float shv = g_bn2[(b * 32 + c) * 2 + 1];
            float y = fmaf(tile[vi * 33 + c], scv, shv);
            out[((size_t)b * 32 + c) * V2 + v] = (y >= 0.f) ? y : SLOPE * y;
        }
    }
}

// ---------------- launch ----------------
extern "C" void kernel_launch(void* const* d_in, const int* in_sizes, int n_in,
                              void* d_out, int out_size)
{
    const float* x1   = (const float*)d_in[0];
    const float* x2   = (const float*)d_in[1];
    const int* neigh  = (const int*)d_in[2];
    const int* top    = (const int*)d_in[3];
    const int* down   = (const int*)d_in[4];
    const float* W_up = (const float*)d_in[5];
    const float* b_up = (const float*)d_in[6];
    const float* W1   = (const float*)d_in[7];
    const float* b1   = (const float*)d_in[8];
    const float* g1   = (const float*)d_in[9];
    const float* be1  = (const float*)d_in[10];
    const float* W2   = (const float*)d_in[11];
    const float* b2   = (const float*)d_in[12];
    const float* g2   = (const float*)d_in[13];
    const float* be2  = (const float*)d_in[14];
    float* out = (float*)d_out;

    const size_t up_smem = (size_t)(64 * 225 + 224) * 4;
    const size_t c1_smem = (size_t)(448 * WPAD + 8 * 448 * 4) * 4;
    const size_t c2_smem = (size_t)(224 * WPAD + 8 * 224 * 4) * 4;
    cudaFuncSetAttribute(k_upconv, cudaFuncAttributeMaxDynamicSharedMemorySize, (int)up_smem);
    cudaFuncSetAttribute(k_conv1, cudaFuncAttributeMaxDynamicSharedMemorySize, (int)c1_smem);
    cudaFuncSetAttribute(k_conv2, cudaFuncAttributeMaxDynamicSharedMemorySize, (int)c2_smem);

    dim3 gxt((V1 + 31) / 32, NB);
    k_xt<<<gxt, 256>>>(x1);

    dim3 gup((V2 + UP_VPB - 1) / UP_VPB, NB);
    k_upconv<<<gup, 256, up_smem>>>(x2, top, down, W_up, b_up);

    dim3 gc1((V2 + C1_VPB - 1) / C1_VPB, NB);
    k_conv1<<<gc1, 256, c1_smem>>>(neigh, W1, b1);

    dim3 gst(32, NB);
    k_stats<<<gst, 256>>>(0, g1, be1);

    k_conv2<<<gc1, 256, c2_smem>>>(neigh, W2, b2);

    k_stats<<<gst, 256>>>(1, g2, be2);

    dim3 gfin((V2 + 31) / 32, NB);
    k_final<<<gfin, 256>>>(out);
}

// round 3
// speedup vs baseline: 1.3040x; 1.3040x over previous
#include <cuda_runtime.h>
#include <cstdint>
#include <cstddef>

#define NB 4
#define V1 40962
#define V2 163842
#define EPSF 1e-5f
#define SLOPE 0.2f

// ---------------- static scratch ----------------
__device__ float g_x1t[(size_t)NB * V1 * 64];    // x1 transposed (B,V1,64)
__device__ float g_raw[(size_t)NB * V1 * 224];   // upconv pre-scatter (= "flat" view)
__device__ float g_y  [(size_t)NB * V2 * 64];    // scatter + skip concat (B,V2,64)
__device__ float g_h1 [(size_t)NB * V2 * 32];    // conv1 pre-BN
__device__ float g_h2 [(size_t)NB * V2 * 32];    // conv2 pre-BN
__device__ float g_s1[NB * 32], g_q1[NB * 32];   // stats accumulators
__device__ float g_s2[NB * 32], g_q2[NB * 32];
__device__ float g_sc1[NB * 32], g_sh1[NB * 32]; // BN scale/shift
__device__ float g_sc2[NB * 32], g_sh2[NB * 32];

extern __shared__ float smem[];

// ---------------- zero stats ----------------
__global__ void k_zero()
{
    int i = threadIdx.x;
    if (i < NB * 32) { g_s1[i] = 0.f; g_q1[i] = 0.f; g_s2[i] = 0.f; g_q2[i] = 0.f; }
}

// ---------------- transpose x1 (B,64,V1) -> (B,V1,64) ----------------
__global__ __launch_bounds__(256) void k_xt(const float* __restrict__ x1)
{
    __shared__ float tile[64 * 33];
    int b = blockIdx.y;
    int v0 = blockIdx.x * 32;
    const float* src = x1 + (size_t)b * 64 * V1;
    float* dst = g_x1t + (size_t)b * V1 * 64;
    int tid = threadIdx.x;
    for (int idx = tid; idx < 64 * 32; idx += 256) {
        int vl = idx & 31, c = idx >> 5;
        int v = v0 + vl;
        tile[c * 33 + vl] = (v < V1) ? src[(size_t)c * V1 + v] : 0.f;
    }
    __syncthreads();
    for (int idx = tid; idx < 64 * 32; idx += 256) {
        int c = idx & 63, vl = idx >> 6;
        int v = v0 + vl;
        if (v < V1) dst[(size_t)v * 64 + c] = tile[c * 33 + vl];
    }
}

// ---------------- upconv GEMM: raw[v][0:224] = x1t[v] @ W_up^T + b_up ----------------
__global__ __launch_bounds__(256) void k_upgemm(const float* __restrict__ W_up,
                                                const float* __restrict__ b_up)
{
    float* Wt = smem;                     // [64][224]  Wt[k*224+r] = W_up[r][k]
    float* bs = Wt + 64 * 224;            // [224]
    float* mblk = bs + 224;               // 8 x [32][65]
    float* sblk = mblk + 8 * 32 * 65;     // 8 x [32][33] staging
    int tid = threadIdx.x, b = blockIdx.y;

    for (int i = tid; i < 224 * 64; i += 256) {
        int r = i >> 6, k = i & 63;
        Wt[k * 224 + r] = W_up[i];
    }
    for (int i = tid; i < 224; i += 256) bs[i] = b_up[i];
    __syncthreads();

    int warp = tid >> 5, lane = tid & 31;
    int tb = (blockIdx.x * 8 + warp) * 32;
    if (tb >= V1) return;
    int nvalid = V1 - tb; if (nvalid > 32) nvalid = 32;
    float* m = mblk + warp * 32 * 65;
    float* st = sblk + warp * 32 * 33;
    const float* xb = g_x1t + (size_t)b * V1 * 64;
    float* rb = g_raw + (size_t)b * V1 * 224;

    // load x tile (32 vertices x 64 ch)
#pragma unroll
    for (int r = 0; r < 16; ++r) {
        int v = 2 * r + (lane >> 4);
        int c = 4 * (lane & 15);
        float4 x4 = make_float4(0.f, 0.f, 0.f, 0.f);
        if (v < nvalid) x4 = *(const float4*)(xb + (size_t)(tb + v) * 64 + c);
        m[v * 65 + c] = x4.x; m[v * 65 + c + 1] = x4.y;
        m[v * 65 + c + 2] = x4.z; m[v * 65 + c + 3] = x4.w;
    }
    __syncwarp();

    const float* mp = m + lane * 65;
    for (int rg = 0; rg < 7; ++rg) {
        float acc[32];
#pragma unroll
        for (int q = 0; q < 8; ++q) {
            float4 b4 = *(const float4*)(bs + rg * 32 + 4 * q);
            acc[4 * q] = b4.x; acc[4 * q + 1] = b4.y;
            acc[4 * q + 2] = b4.z; acc[4 * q + 3] = b4.w;
        }
        const float* wp = Wt + rg * 32;
#pragma unroll 4
        for (int k = 0; k < 64; ++k) {
            float xm = mp[k];
            const float* w = wp + k * 224;
#pragma unroll
            for (int q = 0; q < 8; ++q) {
                float4 w4 = *(const float4*)(w + 4 * q);
                acc[4 * q]     = fmaf(xm, w4.x, acc[4 * q]);
                acc[4 * q + 1] = fmaf(xm, w4.y, acc[4 * q + 1]);
                acc[4 * q + 2] = fmaf(xm, w4.z, acc[4 * q + 2]);
                acc[4 * q + 3] = fmaf(xm, w4.w, acc[4 * q + 3]);
            }
        }
#pragma unroll
        for (int c = 0; c < 32; ++c) st[lane * 33 + c] = acc[c];
        __syncwarp();
#pragma unroll
        for (int r = 0; r < 8; ++r) {
            int v = 4 * r + (lane >> 3);
            int c = 4 * (lane & 7);
            if (v < nvalid) {
                float4 o = make_float4(st[v * 33 + c], st[v * 33 + c + 1],
                                       st[v * 33 + c + 2], st[v * 33 + c + 3]);
                *(float4*)(rb + (size_t)(tb + v) * 224 + rg * 32 + c) = o;
            }
        }
        __syncwarp();
    }
}

// ---------------- scatter + skip concat -> y (B,V2,64) ----------------
__global__ __launch_bounds__(256) void k_scatter(const float* __restrict__ x2,
                                                 const int* __restrict__ top,
                                                 const int* __restrict__ down)
{
    int b = blockIdx.y;
    int v0 = blockIdx.x * 256;
    const float* fb = g_raw + (size_t)b * V1 * 224;   // flat (V1*7, 32) view
    float* yb = g_y + (size_t)b * V2 * 64;
    int tid = threadIdx.x;
    for (int pass = 0; pass < 8; ++pass) {
        int vl = pass * 32 + (tid >> 3);
        int v = v0 + vl;
        int c0 = 4 * (tid & 7);
        if (v < V1) {
            int t = top[v];
            float4 f = *(const float4*)(fb + (size_t)t * 32 + c0);
            *(float4*)(yb + (size_t)v * 64 + c0) = f;
        } else if (v < V2) {
            int n = v - V1;
            int r = down[2 * n + (c0 >= 16 ? 1 : 0)];
            int base = (2 * c0) & 31;
            float4 f0 = *(const float4*)(fb + (size_t)r * 32 + base);
            float4 f1 = *(const float4*)(fb + (size_t)r * 32 + base + 4);
            float4 o;
            o.x = 0.5f * (f0.x + f0.y); o.y = 0.5f * (f0.z + f0.w);
            o.z = 0.5f * (f1.x + f1.y); o.w = 0.5f * (f1.z + f1.w);
            *(float4*)(yb + (size_t)v * 64 + c0) = o;
        }
    }
    const float* x2b = x2 + (size_t)b * 32 * V2;
    for (int i = tid; i < 256 * 32; i += 256) {
        int c = i & 31, vl = i >> 5;
        int v = v0 + vl;
        if (v < V2) yb[(size_t)v * 64 + 32 + c] = x2b[(size_t)c * V2 + v];
    }
}

// ---------------- conv1: gather 7x64 + GEMM 448->32 + stats ----------------
__global__ __launch_bounds__(256) void k_conv1(const int* __restrict__ neigh,
                                               const float* __restrict__ W1,
                                               const float* __restrict__ b1)
{
    float* Wt = smem;                       // [448][32]
    float* mblk = Wt + 448 * 32;            // 8 x [32][65]
    int* nblk = (int*)(mblk + 8 * 32 * 65); // 8 x [32*7]
    int tid = threadIdx.x, b = blockIdx.y;
    for (int i = tid; i < 32 * 448; i += 256) {
        int c = i / 448, k = i % 448;
        Wt[k * 32 + c] = W1[i];
    }
    __syncthreads();

    int warp = tid >> 5, lane = tid & 31;
    int tb = (blockIdx.x * 8 + warp) * 32;
    if (tb >= V2) return;
    int nvalid = V2 - tb; if (nvalid > 32) nvalid = 32;
    float* m = mblk + warp * 32 * 65;
    int* nidx = nblk + warp * 224;
    const float* yb = g_y + (size_t)b * V2 * 64;
    float* hb = g_h1 + (size_t)b * V2 * 32;

    {
        int v = lane;
#pragma unroll
        for (int q = 0; q < 7; ++q)
            nidx[v * 7 + q] = (v < nvalid) ? neigh[(size_t)(tb + v) * 7 + q] : 0;
    }
    float acc[32];
#pragma unroll
    for (int q = 0; q < 8; ++q) {
        float4 b4 = *(const float4*)(b1 + 4 * q);
        acc[4 * q] = b4.x; acc[4 * q + 1] = b4.y;
        acc[4 * q + 2] = b4.z; acc[4 * q + 3] = b4.w;
    }
    __syncwarp();

    const float* mp = m + lane * 65;
    for (int j = 0; j < 7; ++j) {
#pragma unroll
        for (int h = 0; h < 2; ++h) {
#pragma unroll
            for (int r = 0; r < 8; ++r) {
                int v = 4 * r + (lane >> 3);
                int c = 32 * h + 4 * (lane & 7);
                int nb = nidx[v * 7 + j];
                float4 f = *(const float4*)(yb + (size_t)nb * 64 + c);
                m[v * 65 + c] = f.x; m[v * 65 + c + 1] = f.y;
                m[v * 65 + c + 2] = f.z; m[v * 65 + c + 3] = f.w;
            }
        }
        __syncwarp();
        const float* wp = Wt + j * 64 * 32;
#pragma unroll 4
        for (int k = 0; k < 64; ++k) {
            float xm = mp[k];
            const float* w = wp + k * 32;
#pragma unroll
            for (int q = 0; q < 8; ++q) {
                float4 w4 = *(const float4*)(w + 4 * q);
                acc[4 * q]     = fmaf(xm, w4.x, acc[4 * q]);
                acc[4 * q + 1] = fmaf(xm, w4.y, acc[4 * q + 1]);
                acc[4 * q + 2] = fmaf(xm, w4.z, acc[4 * q + 2]);
                acc[4 * q + 3] = fmaf(xm, w4.w, acc[4 * q + 3]);
            }
        }
        __syncwarp();
    }
    if (lane >= nvalid) {
#pragma unroll
        for (int c = 0; c < 32; ++c) acc[c] = 0.f;
    }
#pragma unroll
    for (int c = 0; c < 32; ++c) m[lane * 65 + c] = acc[c];
    __syncwarp();
#pragma unroll
    for (int r = 0; r < 8; ++r) {
        int v = 4 * r + (lane >> 3);
        int c = 4 * (lane & 7);
        if (v < nvalid) {
            float4 o = make_float4(m[v * 65 + c], m[v * 65 + c + 1],
                                   m[v * 65 + c + 2], m[v * 65 + c + 3]);
            *(float4*)(hb + (size_t)(tb + v) * 32 + c) = o;
        }
    }
    float s = 0.f, q = 0.f;
#pragma unroll 8
    for (int v = 0; v < 32; ++v) {
        float x = m[v * 65 + lane];
        s += x;
        q = fmaf(x, x, q);
    }
    atomicAdd(&g_s1[b * 32 + lane], s);
    atomicAdd(&g_q1[b * 32 + lane], q);
}

// ---------------- BN finalize ----------------
__global__ void k_bnfin(int which, const float* __restrict__ g, const float* __restrict__ be)
{
    int i = threadIdx.x;
    if (i >= NB * 32) return;
    int c = i & 31;
    float s = which ? g_s2[i] : g_s1[i];
    float q = which ? g_q2[i] : g_q1[i];
    float mean = s / (float)V2;
    float var = q / (float)V2 - mean * mean;
    float scale = g[c] * rsqrtf(var + EPSF);
    float shift = be[c] - mean * scale;
    if (which) { g_sc2[i] = scale; g_sh2[i] = shift; }
    else       { g_sc1[i] = scale; g_sh1[i] = shift; }
}

// ---------------- conv2: BN1+LReLU folded gather 7x32 + GEMM 224->32 + stats ----------------
__global__ __launch_bounds__(256) void k_conv2(const int* __restrict__ neigh,
                                               const float* __restrict__ W2,
                                               const float* __restrict__ b2)
{
    float* Wt = smem;                       // [224][32]
    float* mblk = Wt + 224 * 32;            // 8 x [32][33]
    int* nblk = (int*)(mblk + 8 * 32 * 33);
    int tid = threadIdx.x, b = blockIdx.y;
    for (int i = tid; i < 32 * 224; i += 256) {
        int c = i / 224, k = i % 224;
        Wt[k * 32 + c] = W2[i];
    }
    __syncthreads();

    int warp = tid >> 5, lane = tid & 31;
    int tb = (blockIdx.x * 8 + warp) * 32;
    if (tb >= V2) return;
    int nvalid = V2 - tb; if (nvalid > 32) nvalid = 32;
    float* m = mblk + warp * 32 * 33;
    int* nidx = nblk + warp * 224;
    const float* h1b = g_h1 + (size_t)b * V2 * 32;
    float* h2b = g_h2 + (size_t)b * V2 * 32;

    {
        int v = lane;
#pragma unroll
        for (int q = 0; q < 7; ++q)
            nidx[v * 7 + q] = (v < nvalid) ? neigh[(size_t)(tb + v) * 7 + q] : 0;
    }
    int cg = 4 * (lane & 7);
    float4 sc4 = *(const float4*)(g_sc1 + b * 32 + cg);
    float4 sh4 = *(const float4*)(g_sh1 + b * 32 + cg);

    float acc[32];
#pragma unroll
    for (int q = 0; q < 8; ++q) {
        float4 b4 = *(const float4*)(b2 + 4 * q);
        acc[4 * q] = b4.x; acc[4 * q + 1] = b4.y;
        acc[4 * q + 2] = b4.z; acc[4 * q + 3] = b4.w;
    }
    __syncwarp();

    const float* mp = m + lane * 33;
    for (int j = 0; j < 7; ++j) {
#pragma unroll
        for (int r = 0; r < 8; ++r) {
            int v = 4 * r + (lane >> 3);
            int nb = nidx[v * 7 + j];
            float4 f = *(const float4*)(h1b + (size_t)nb * 32 + cg);
            f.x = fmaf(f.x, sc4.x, sh4.x); f.x = f.x >= 0.f ? f.x : SLOPE * f.x;
            f.y = fmaf(f.y, sc4.y, sh4.y); f.y = f.y >= 0.f ? f.y : SLOPE * f.y;
            f.z = fmaf(f.z, sc4.z, sh4.z); f.z = f.z >= 0.f ? f.z : SLOPE * f.z;
            f.w = fmaf(f.w, sc4.w, sh4.w); f.w = f.w >= 0.f ? f.w : SLOPE * f.w;
            m[v * 33 + cg] = f.x; m[v * 33 + cg + 1] = f.y;
            m[v * 33 + cg + 2] = f.z; m[v * 33 + cg + 3] = f.w;
        }
        __syncwarp();
        const float* wp = Wt + j * 32 * 32;
#pragma unroll 4
        for (int k = 0; k < 32; ++k) {
            float xm = mp[k];
            const float* w = wp + k * 32;
#pragma unroll
            for (int q = 0; q < 8; ++q) {
                float4 w4 = *(const float4*)(w + 4 * q);
                acc[4 * q]     = fmaf(xm, w4.x, acc[4 * q]);
                acc[4 * q + 1] = fmaf(xm, w4.y, acc[4 * q + 1]);
                acc[4 * q + 2] = fmaf(xm, w4.z, acc[4 * q + 2]);
                acc[4 * q + 3] = fmaf(xm, w4.w, acc[4 * q + 3]);
            }
        }
        __syncwarp();
    }
    if (lane >= nvalid) {
#pragma unroll
        for (int c = 0; c < 32; ++c) acc[c] = 0.f;
    }
#pragma unroll
    for (int c = 0; c < 32; ++c) m[lane * 33 + c] = acc[c];
    __syncwarp();
#pragma unroll
    for (int r = 0; r < 8; ++r) {
        int v = 4 * r + (lane >> 3);
        int c = 4 * (lane & 7);
        if (v < nvalid) {
            float4 o = make_float4(m[v * 33 + c], m[v * 33 + c + 1],
                                   m[v * 33 + c + 2], m[v * 33 + c + 3]);
            *(float4*)(h2b + (size_t)(tb + v) * 32 + c) = o;
        }
    }
    float s = 0.f, q = 0.f;
#pragma unroll 8
    for (int v = 0; v < 32; ++v) {
        float x = m[v * 33 + lane];
        s += x;
        q = fmaf(x, x, q);
    }
    atomicAdd(&g_s2[b * 32 + lane], s);
    atomicAdd(&g_q2[b * 32 + lane], q);
}

// ---------------- BN2 + LReLU + transpose out (B,32,V2) ----------------
__global__ __launch_bounds__(256) void k_final(float* __restrict__ out)
{
    __shared__ float tile[32 * 33];
    int b = blockIdx.y, v0 = blockIdx.x * 32;
    const float* hb = g_h2 + (size_t)b * V2 * 32;
    int tid = threadIdx.x;
    for (int i = tid; i < 1024; i += 256) {
        int c = i & 31, vi = i >> 5;
        int v = v0 + vi;
        tile[vi * 33 + c] = (v < V2) ? hb[(size_t)v * 32 + c] : 0.f;
    }
    __syncthreads();
    for (int i = tid; i < 1024; i += 256) {
        int vi = i & 31, c = i >> 5;
        int v = v0 + vi;
        if (v < V2) {
            float y = fmaf(tile[vi * 33 + c], g_sc2[b * 32 + c], g_sh2[b * 32 + c]);
            out[((size_t)b * 32 + c) * V2 + v] = (y >= 0.f) ? y : SLOPE * y;
        }
    }
}

// ---------------- launch ----------------
extern "C" void kernel_launch(void* const* d_in, const int* in_sizes, int n_in,
                              void* d_out, int out_size)
{
    const float* x1   = (const float*)d_in[0];
    const float* x2   = (const float*)d_in[1];
    const int* neigh  = (const int*)d_in[2];
    const int* top    = (const int*)d_in[3];
    const int* down   = (const int*)d_in[4];
    const float* W_up = (const float*)d_in[5];
    const float* b_up = (const float*)d_in[6];
    const float* W1   = (const float*)d_in[7];
    const float* b1   = (const float*)d_in[8];
    const float* g1   = (const float*)d_in[9];
    const float* be1  = (const float*)d_in[10];
    const float* W2   = (const float*)d_in[11];
    const float* b2   = (const float*)d_in[12];
    const float* g2   = (const float*)d_in[13];
    const float* be2  = (const float*)d_in[14];
    float* out = (float*)d_out;

    const size_t ug_smem = (size_t)(64 * 224 + 224 + 8 * 32 * 65 + 8 * 32 * 33) * 4;
    const size_t c1_smem = (size_t)(448 * 32 + 8 * 32 * 65 + 8 * 224) * 4;
    const size_t c2_smem = (size_t)(224 * 32 + 8 * 32 * 33 + 8 * 224) * 4;
    cudaFuncSetAttribute(k_upgemm, cudaFuncAttributeMaxDynamicSharedMemorySize, (int)ug_smem);
    cudaFuncSetAttribute(k_conv1, cudaFuncAttributeMaxDynamicSharedMemorySize, (int)c1_smem);
    cudaFuncSetAttribute(k_conv2, cudaFuncAttributeMaxDynamicSharedMemorySize, (int)c2_smem);

    k_zero<<<1, 128>>>();

    dim3 gxt((V1 + 31) / 32, NB);
    k_xt<<<gxt, 256>>>(x1);

    int ug_tiles = (V1 + 31) / 32;
    dim3 gug((ug_tiles + 7) / 8, NB);
    k_upgemm<<<gug, 256, ug_smem>>>(W_up, b_up);

    dim3 gsc((V2 + 255) / 256, NB);
    k_scatter<<<gsc, 256>>>(x2, top, down);

    int cv_tiles = (V2 + 31) / 32;
    dim3 gcv((cv_tiles + 7) / 8, NB);
    k_conv1<<<gcv, 256, c1_smem>>>(neigh, W1, b1);

    k_bnfin<<<1, 128>>>(0, g1, be1);

    k_conv2<<<gcv, 256, c2_smem>>>(neigh, W2, b2);

    k_bnfin<<<1, 128>>>(1, g2, be2);

    dim3 gfin((V2 + 31) / 32, NB);
    k_final<<<gfin, 256>>>(out);
}

// round 4
// speedup vs baseline: 1.8248x; 1.3994x over previous
#include <cuda_runtime.h>
#include <cstdint>
#include <cstddef>

#define NB 4
#define V1 40962
#define V2 163842
#define EPSF 1e-5f
#define SLOPE 0.2f

// ---------------- static scratch ----------------
__device__ float g_raw[(size_t)NB * V1 * 224];   // upconv pre-scatter ("flat" view)
__device__ float g_y  [(size_t)NB * V2 * 64];    // scatter + skip concat (B,V2,64)
__device__ float g_h1 [(size_t)NB * V2 * 32];    // conv1 pre-BN
__device__ float g_h2 [(size_t)NB * V2 * 32];    // conv2 pre-BN
__device__ float g_s1[NB * 32], g_q1[NB * 32];
__device__ float g_s2[NB * 32], g_q2[NB * 32];
__device__ float g_sc1[NB * 32], g_sh1[NB * 32];
__device__ float g_sc2[NB * 32], g_sh2[NB * 32];

extern __shared__ float smem[];

__global__ void k_zero()
{
    int i = threadIdx.x;
    if (i < NB * 32) { g_s1[i] = 0.f; g_q1[i] = 0.f; g_s2[i] = 0.f; g_q2[i] = 0.f; }
}

// ---------------- upconv GEMM (x1 read directly, transposed via smem) ----------------
__global__ __launch_bounds__(256) void k_upgemm(const float* __restrict__ x1,
                                                const float* __restrict__ W_up,
                                                const float* __restrict__ b_up)
{
    float* Wt = smem;                     // [64][224]
    float* bs = Wt + 64 * 224;            // [224]
    float* mblk = bs + 224;               // 8 x [32][65]
    float* sblk = mblk + 8 * 32 * 65;     // 8 x [32][33]
    int tid = threadIdx.x, b = blockIdx.y;

    for (int i = tid; i < 224 * 64; i += 256) {
        int r = i >> 6, k = i & 63;
        Wt[k * 224 + r] = W_up[i];
    }
    for (int i = tid; i < 224; i += 256) bs[i] = b_up[i];
    __syncthreads();

    int warp = tid >> 5, lane = tid & 31;
    int tb = (blockIdx.x * 8 + warp) * 32;
    if (tb >= V1) return;
    int nvalid = V1 - tb; if (nvalid > 32) nvalid = 32;
    float* m = mblk + warp * 32 * 65;
    float* st = sblk + warp * 32 * 33;
    const float* x1b = x1 + (size_t)b * 64 * V1;
    float* rb = g_raw + (size_t)b * V1 * 224;

    // x tile: coalesced read over vertices, conflict-free strided STS
    {
        int v = tb + lane;
        bool ok = (lane < nvalid);
#pragma unroll 8
        for (int c = 0; c < 64; ++c)
            m[lane * 65 + c] = ok ? x1b[(size_t)c * V1 + v] : 0.f;
    }
    __syncwarp();

    const float* mp = m + lane * 65;
    for (int rg = 0; rg < 7; ++rg) {
        float acc[32];
#pragma unroll
        for (int q = 0; q < 8; ++q) {
            float4 b4 = *(const float4*)(bs + rg * 32 + 4 * q);
            acc[4 * q] = b4.x; acc[4 * q + 1] = b4.y;
            acc[4 * q + 2] = b4.z; acc[4 * q + 3] = b4.w;
        }
        const float* wp = Wt + rg * 32;
#pragma unroll 8
        for (int k = 0; k < 64; ++k) {
            float xm = mp[k];
            const float* w = wp + k * 224;
#pragma unroll
            for (int q = 0; q < 8; ++q) {
                float4 w4 = *(const float4*)(w + 4 * q);
                acc[4 * q]     = fmaf(xm, w4.x, acc[4 * q]);
                acc[4 * q + 1] = fmaf(xm, w4.y, acc[4 * q + 1]);
                acc[4 * q + 2] = fmaf(xm, w4.z, acc[4 * q + 2]);
                acc[4 * q + 3] = fmaf(xm, w4.w, acc[4 * q + 3]);
            }
        }
#pragma unroll
        for (int c = 0; c < 32; ++c) st[lane * 33 + c] = acc[c];
        __syncwarp();
#pragma unroll
        for (int r = 0; r < 8; ++r) {
            int v = 4 * r + (lane >> 3);
            int c = 4 * (lane & 7);
            if (v < nvalid) {
                float4 o = make_float4(st[v * 33 + c], st[v * 33 + c + 1],
                                       st[v * 33 + c + 2], st[v * 33 + c + 3]);
                *(float4*)(rb + (size_t)(tb + v) * 224 + rg * 32 + c) = o;
            }
        }
        __syncwarp();
    }
}

// ---------------- scatter + skip concat ----------------
__global__ __launch_bounds__(256) void k_scatter(const float* __restrict__ x2,
                                                 const int* __restrict__ top,
                                                 const int* __restrict__ down)
{
    int b = blockIdx.y;
    int v0 = blockIdx.x * 256;
    const float* fb = g_raw + (size_t)b * V1 * 224;
    float* yb = g_y + (size_t)b * V2 * 64;
    int tid = threadIdx.x;
    for (int pass = 0; pass < 8; ++pass) {
        int vl = pass * 32 + (tid >> 3);
        int v = v0 + vl;
        int c0 = 4 * (tid & 7);
        if (v < V1) {
            int t = top[v];
            float4 f = *(const float4*)(fb + (size_t)t * 32 + c0);
            *(float4*)(yb + (size_t)v * 64 + c0) = f;
        } else if (v < V2) {
            int n = v - V1;
            int r = down[2 * n + (c0 >= 16 ? 1 : 0)];
            int base = (2 * c0) & 31;
            float4 f0 = *(const float4*)(fb + (size_t)r * 32 + base);
            float4 f1 = *(const float4*)(fb + (size_t)r * 32 + base + 4);
            float4 o;
            o.x = 0.5f * (f0.x + f0.y); o.y = 0.5f * (f0.z + f0.w);
            o.z = 0.5f * (f1.x + f1.y); o.w = 0.5f * (f1.z + f1.w);
            *(float4*)(yb + (size_t)v * 64 + c0) = o;
        }
    }
    const float* x2b = x2 + (size_t)b * 32 * V2;
    for (int i = tid; i < 256 * 32; i += 256) {
        int c = i & 31, vl = i >> 5;
        int v = v0 + vl;
        if (v < V2) yb[(size_t)v * 64 + 32 + c] = x2b[(size_t)c * V2 + v];
    }
}

// ---------------- conv1: pipelined gather (14 chunks of 32k) + GEMM + stats ----------------
__global__ __launch_bounds__(256, 2) void k_conv1(const int* __restrict__ neigh,
                                                  const float* __restrict__ W1,
                                                  const float* __restrict__ b1)
{
    float* Wt = smem;                        // [448][32]
    float* mblk = Wt + 448 * 32;             // 8 x [32][33]
    int* nblk = (int*)(mblk + 8 * 32 * 33);  // 8 x 224
    int tid = threadIdx.x, b = blockIdx.y;
    for (int i = tid; i < 32 * 448; i += 256) {
        int c = i / 448, k = i % 448;
        Wt[k * 32 + c] = W1[i];
    }
    __syncthreads();

    int warp = tid >> 5, lane = tid & 31;
    int tb = (blockIdx.x * 8 + warp) * 32;
    if (tb >= V2) return;
    int nvalid = V2 - tb; if (nvalid > 32) nvalid = 32;
    float* m = mblk + warp * 32 * 33;
    int* nidx = nblk + warp * 224;
    const float* yb = g_y + (size_t)b * V2 * 64;
    float* hb = g_h1 + (size_t)b * V2 * 32;

    {
        int vv = tb + (lane < nvalid ? lane : 0);
#pragma unroll
        for (int q = 0; q < 7; ++q)
            nidx[lane * 7 + q] = neigh[(size_t)vv * 7 + q];
    }
    __syncwarp();

    float acc[32];
#pragma unroll
    for (int q = 0; q < 8; ++q) {
        float4 b4 = *(const float4*)(b1 + 4 * q);
        acc[4 * q] = b4.x; acc[4 * q + 1] = b4.y;
        acc[4 * q + 2] = b4.z; acc[4 * q + 3] = b4.w;
    }

    int rsel = lane >> 3;
    int cg = 4 * (lane & 7);
    const float* mp = m + lane * 33;
    float4 pf[8];

    // prefetch chunk 0
    {
        int j = 0, bc = cg;
#pragma unroll
        for (int r = 0; r < 8; ++r) {
            int nb = nidx[(4 * r + rsel) * 7 + j];
            pf[r] = *(const float4*)(yb + (size_t)nb * 64 + bc);
        }
    }

    for (int ch = 0; ch < 14; ++ch) {
        __syncwarp();
#pragma unroll
        for (int r = 0; r < 8; ++r) {
            int v = 4 * r + rsel;
            m[v * 33 + cg]     = pf[r].x;
            m[v * 33 + cg + 1] = pf[r].y;
            m[v * 33 + cg + 2] = pf[r].z;
            m[v * 33 + cg + 3] = pf[r].w;
        }
        __syncwarp();
        if (ch < 13) {
            int nc = ch + 1;
            int j = nc >> 1;
            int bc = ((nc & 1) << 5) + cg;
#pragma unroll
            for (int r = 0; r < 8; ++r) {
                int nb = nidx[(4 * r + rsel) * 7 + j];
                pf[r] = *(const float4*)(yb + (size_t)nb * 64 + bc);
            }
        }
        const float* wp = Wt + ch * 32 * 32;
#pragma unroll 8
        for (int kk = 0; kk < 32; ++kk) {
            float xm = mp[kk];
            const float* w = wp + kk * 32;
#pragma unroll
            for (int q = 0; q < 8; ++q) {
                float4 w4 = *(const float4*)(w + 4 * q);
                acc[4 * q]     = fmaf(xm, w4.x, acc[4 * q]);
                acc[4 * q + 1] = fmaf(xm, w4.y, acc[4 * q + 1]);
                acc[4 * q + 2] = fmaf(xm, w4.z, acc[4 * q + 2]);
                acc[4 * q + 3] = fmaf(xm, w4.w, acc[4 * q + 3]);
            }
        }
    }
    __syncwarp();

    if (lane >= nvalid) {
#pragma unroll
        for (int c = 0; c < 32; ++c) acc[c] = 0.f;
    }
#pragma unroll
    for (int c = 0; c < 32; ++c) m[lane * 33 + c] = acc[c];
    __syncwarp();
#pragma unroll
    for (int r = 0; r < 8; ++r) {
        int v = 4 * r + rsel;
        if (v < nvalid) {
            float4 o = make_float4(m[v * 33 + cg], m[v * 33 + cg + 1],
                                   m[v * 33 + cg + 2], m[v * 33 + cg + 3]);
            *(float4*)(hb + (size_t)(tb + v) * 32 + cg) = o;
        }
    }
    float s = 0.f, q = 0.f;
#pragma unroll 8
    for (int v = 0; v < 32; ++v) {
        float x = m[v * 33 + lane];
        s += x;
        q = fmaf(x, x, q);
    }
    atomicAdd(&g_s1[b * 32 + lane], s);
    atomicAdd(&g_q1[b * 32 + lane], q);
}

// ---------------- BN finalize ----------------
__global__ void k_bnfin(int which, const float* __restrict__ g, const float* __restrict__ be)
{
    int i = threadIdx.x;
    if (i >= NB * 32) return;
    int c = i & 31;
    float s = which ? g_s2[i] : g_s1[i];
    float q = which ? g_q2[i] : g_q1[i];
    float mean = s / (float)V2;
    float var = q / (float)V2 - mean * mean;
    float scale = g[c] * rsqrtf(var + EPSF);
    float shift = be[c] - mean * scale;
    if (which) { g_sc2[i] = scale; g_sh2[i] = shift; }
    else       { g_sc1[i] = scale; g_sh1[i] = shift; }
}

// ---------------- conv2: pipelined (7 chunks), BN1+LReLU folded, + stats ----------------
__global__ __launch_bounds__(256, 2) void k_conv2(const int* __restrict__ neigh,
                                                  const float* __restrict__ W2,
                                                  const float* __restrict__ b2)
{
    float* Wt = smem;                        // [224][32]
    float* mblk = Wt + 224 * 32;             // 8 x [32][33]
    int* nblk = (int*)(mblk + 8 * 32 * 33);
    int tid = threadIdx.x, b = blockIdx.y;
    for (int i = tid; i < 32 * 224; i += 256) {
        int c = i / 224, k = i % 224;
        Wt[k * 32 + c] = W2[i];
    }
    __syncthreads();

    int warp = tid >> 5, lane = tid & 31;
    int tb = (blockIdx.x * 8 + warp) * 32;
    if (tb >= V2) return;
    int nvalid = V2 - tb; if (nvalid > 32) nvalid = 32;
    float* m = mblk + warp * 32 * 33;
    int* nidx = nblk + warp * 224;
    const float* h1b = g_h1 + (size_t)b * V2 * 32;
    float* h2b = g_h2 + (size_t)b * V2 * 32;

    {
        int vv = tb + (lane < nvalid ? lane : 0);
#pragma unroll
        for (int q = 0; q < 7; ++q)
            nidx[lane * 7 + q] = neigh[(size_t)vv * 7 + q];
    }
    __syncwarp();

    int rsel = lane >> 3;
    int cg = 4 * (lane & 7);
    float4 sc4 = *(const float4*)(g_sc1 + b * 32 + cg);
    float4 sh4 = *(const float4*)(g_sh1 + b * 32 + cg);

    float acc[32];
#pragma unroll
    for (int q = 0; q < 8; ++q) {
        float4 b4 = *(const float4*)(b2 + 4 * q);
        acc[4 * q] = b4.x; acc[4 * q + 1] = b4.y;
        acc[4 * q + 2] = b4.z; acc[4 * q + 3] = b4.w;
    }

    const float* mp = m + lane * 33;
    float4 pf[8];
#pragma unroll
    for (int r = 0; r < 8; ++r) {
        int nb = nidx[(4 * r + rsel) * 7 + 0];
        pf[r] = *(const float4*)(h1b + (size_t)nb * 32 + cg);
    }

    for (int ch = 0; ch < 7; ++ch) {
        __syncwarp();
#pragma unroll
        for (int r = 0; r < 8; ++r) {
            int v = 4 * r + rsel;
            float4 f = pf[r];
            f.x = fmaf(f.x, sc4.x, sh4.x); f.x = f.x >= 0.f ? f.x : SLOPE * f.x;
            f.y = fmaf(f.y, sc4.y, sh4.y); f.y = f.y >= 0.f ? f.y : SLOPE * f.y;
            f.z = fmaf(f.z, sc4.z, sh4.z); f.z = f.z >= 0.f ? f.z : SLOPE * f.z;
            f.w = fmaf(f.w, sc4.w, sh4.w); f.w = f.w >= 0.f ? f.w : SLOPE * f.w;
            m[v * 33 + cg]     = f.x;
            m[v * 33 + cg + 1] = f.y;
            m[v * 33 + cg + 2] = f.z;
            m[v * 33 + cg + 3] = f.w;
        }
        __syncwarp();
        if (ch < 6) {
            int j = ch + 1;
#pragma unroll
            for (int r = 0; r < 8; ++r) {
                int nb = nidx[(4 * r + rsel) * 7 + j];
                pf[r] = *(const float4*)(h1b + (size_t)nb * 32 + cg);
            }
        }
        const float* wp = Wt + ch * 32 * 32;
#pragma unroll 8
        for (int kk = 0; kk < 32; ++kk) {
            float xm = mp[kk];
            const float* w = wp + kk * 32;
#pragma unroll
            for (int q = 0; q < 8; ++q) {
                float4 w4 = *(const float4*)(w + 4 * q);
                acc[4 * q]     = fmaf(xm, w4.x, acc[4 * q]);
                acc[4 * q + 1] = fmaf(xm, w4.y, acc[4 * q + 1]);
                acc[4 * q + 2] = fmaf(xm, w4.z, acc[4 * q + 2]);
                acc[4 * q + 3] = fmaf(xm, w4.w, acc[4 * q + 3]);
            }
        }
    }
    __syncwarp();

    if (lane >= nvalid) {
#pragma unroll
        for (int c = 0; c < 32; ++c) acc[c] = 0.f;
    }
#pragma unroll
    for (int c = 0; c < 32; ++c) m[lane * 33 + c] = acc[c];
    __syncwarp();
#pragma unroll
    for (int r = 0; r < 8; ++r) {
        int v = 4 * r + rsel;
        if (v < nvalid) {
            float4 o = make_float4(m[v * 33 + cg], m[v * 33 + cg + 1],
                                   m[v * 33 + cg + 2], m[v * 33 + cg + 3]);
            *(float4*)(h2b + (size_t)(tb + v) * 32 + cg) = o;
        }
    }
    float s = 0.f, q = 0.f;
#pragma unroll 8
    for (int v = 0; v < 32; ++v) {
        float x = m[v * 33 + lane];
        s += x;
        q = fmaf(x, x, q);
    }
    atomicAdd(&g_s2[b * 32 + lane], s);
    atomicAdd(&g_q2[b * 32 + lane], q);
}

// ---------------- BN2 + LReLU + transpose out ----------------
__global__ __launch_bounds__(256) void k_final(float* __restrict__ out)
{
    __shared__ float tile[32 * 33];
    int b = blockIdx.y, v0 = blockIdx.x * 32;
    const float* hb = g_h2 + (size_t)b * V2 * 32;
    int tid = threadIdx.x;
    for (int i = tid; i < 1024; i += 256) {
        int c = i & 31, vi = i >> 5;
        int v = v0 + vi;
        tile[vi * 33 + c] = (v < V2) ? hb[(size_t)v * 32 + c] : 0.f;
    }
    __syncthreads();
    for (int i = tid; i < 1024; i += 256) {
        int vi = i & 31, c = i >> 5;
        int v = v0 + vi;
        if (v < V2) {
            float y = fmaf(tile[vi * 33 + c], g_sc2[b * 32 + c], g_sh2[b * 32 + c]);
            out[((size_t)b * 32 + c) * V2 + v] = (y >= 0.f) ? y : SLOPE * y;
        }
    }
}

// ---------------- launch ----------------
extern "C" void kernel_launch(void* const* d_in, const int* in_sizes, int n_in,
                              void* d_out, int out_size)
{
    const float* x1   = (const float*)d_in[0];
    const float* x2   = (const float*)d_in[1];
    const int* neigh  = (const int*)d_in[2];
    const int* top    = (const int*)d_in[3];
    const int* down   = (const int*)d_in[4];
    const float* W_up = (const float*)d_in[5];
    const float* b_up = (const float*)d_in[6];
    const float* W1   = (const float*)d_in[7];
    const float* b1   = (const float*)d_in[8];
    const float* g1   = (const float*)d_in[9];
    const float* be1  = (const float*)d_in[10];
    const float* W2   = (const float*)d_in[11];
    const float* b2   = (const float*)d_in[12];
    const float* g2   = (const float*)d_in[13];
    const float* be2  = (const float*)d_in[14];
    float* out = (float*)d_out;

    const size_t ug_smem = (size_t)(64 * 224 + 224 + 8 * 32 * 65 + 8 * 32 * 33) * 4;
    const size_t c1_smem = (size_t)(448 * 32 + 8 * 32 * 33 + 8 * 224) * 4;
    const size_t c2_smem = (size_t)(224 * 32 + 8 * 32 * 33 + 8 * 224) * 4;
    cudaFuncSetAttribute(k_upgemm, cudaFuncAttributeMaxDynamicSharedMemorySize, (int)ug_smem);
    cudaFuncSetAttribute(k_conv1, cudaFuncAttributeMaxDynamicSharedMemorySize, (int)c1_smem);
    cudaFuncSetAttribute(k_conv2, cudaFuncAttributeMaxDynamicSharedMemorySize, (int)c2_smem);

    k_zero<<<1, 128>>>();

    int ug_tiles = (V1 + 31) / 32;
    dim3 gug((ug_tiles + 7) / 8, NB);
    k_upgemm<<<gug, 256, ug_smem>>>(x1, W_up, b_up);

    dim3 gsc((V2 + 255) / 256, NB);
    k_scatter<<<gsc, 256>>>(x2, top, down);

    int cv_tiles = (V2 + 31) / 32;
    dim3 gcv((cv_tiles + 7) / 8, NB);
    k_conv1<<<gcv, 256, c1_smem>>>(neigh, W1, b1);

    k_bnfin<<<1, 128>>>(0, g1, be1);

    k_conv2<<<gcv, 256, c2_smem>>>(neigh, W2, b2);

    k_bnfin<<<1, 128>>>(1, g2, be2);

    dim3 gfin((V2 + 31) / 32, NB);
    k_final<<<gfin, 256>>>(out);
}

// round 6
// speedup vs baseline: 1.8714x; 1.0255x over previous
#include <cuda_runtime.h>
#include <cstdint>
#include <cstddef>

#define NB 4
#define V1 40962
#define V2 163842
#define EPSF 1e-5f
#define SLOPE 0.2f

// ---------------- static scratch ----------------
__device__ float g_raw[(size_t)NB * V1 * 224];
__device__ float g_y  [(size_t)NB * V2 * 64];
__device__ float g_h1 [(size_t)NB * V2 * 32];
__device__ float g_h2 [(size_t)NB * V2 * 32];
__device__ float g_s1[NB * 32], g_q1[NB * 32];
__device__ float g_s2[NB * 32], g_q2[NB * 32];
__device__ float g_sc1[NB * 32], g_sh1[NB * 32];
__device__ float g_sc2[NB * 32], g_sh2[NB * 32];
// pre-transposed weights (filled by k_prep each call)
__device__ float g_W1t[448 * 32];      // [k][c]
__device__ float g_W2t[224 * 32];      // [k][c]
__device__ float g_Wut[7 * 64 * 32];   // [rg][k][c]

extern __shared__ float smem[];

// ---------------- prep: zero stats + transpose weights ----------------
__global__ __launch_bounds__(256) void k_prep(const float* __restrict__ W1,
                                              const float* __restrict__ W2,
                                              const float* __restrict__ W_up)
{
    int gt = blockIdx.x * 256 + threadIdx.x;
    int stride = gridDim.x * 256;
    if (gt < NB * 32) { g_s1[gt] = 0.f; g_q1[gt] = 0.f; g_s2[gt] = 0.f; g_q2[gt] = 0.f; }
    for (int i = gt; i < 448 * 32; i += stride) {
        int k = i >> 5, c = i & 31;
        g_W1t[i] = W1[c * 448 + k];
    }
    for (int i = gt; i < 224 * 32; i += stride) {
        int k = i >> 5, c = i & 31;
        g_W2t[i] = W2[c * 224 + k];
    }
    for (int i = gt; i < 7 * 64 * 32; i += stride) {
        int rg = i >> 11, rem = i & 2047;
        int k = rem >> 5, c = rem & 31;
        g_Wut[i] = W_up[(rg * 32 + c) * 64 + k];
    }
}

// ---------------- upconv GEMM ----------------
__global__ __launch_bounds__(256) void k_upgemm(const float* __restrict__ x1,
                                                const float* __restrict__ b_up)
{
    float* Wt = smem;                     // [7][64][32]
    float* bs = Wt + 7 * 64 * 32;         // [224]
    float* mblk = bs + 224;               // 8 x [32][65]
    float* sblk = mblk + 8 * 32 * 65;     // 8 x [32][33]
    int tid = threadIdx.x, b = blockIdx.y;

    for (int i = tid; i < 7 * 64 * 32; i += 256) Wt[i] = g_Wut[i];
    for (int i = tid; i < 224; i += 256) bs[i] = b_up[i];
    __syncthreads();

    int warp = tid >> 5, lane = tid & 31;
    int tb = (blockIdx.x * 8 + warp) * 32;
    if (tb >= V1) return;
    int nvalid = V1 - tb; if (nvalid > 32) nvalid = 32;
    float* m = mblk + warp * 32 * 65;
    float* st = sblk + warp * 32 * 33;
    const float* x1b = x1 + (size_t)b * 64 * V1;
    float* rb = g_raw + (size_t)b * V1 * 224;

    {
        int v = tb + lane;
        bool ok = (lane < nvalid);
#pragma unroll 8
        for (int c = 0; c < 64; ++c)
            m[lane * 65 + c] = ok ? x1b[(size_t)c * V1 + v] : 0.f;
    }
    __syncwarp();

    const float* mp = m + lane * 65;
    for (int rg = 0; rg < 7; ++rg) {
        float acc[32];
#pragma unroll
        for (int q = 0; q < 8; ++q) {
            float4 b4 = *(const float4*)(bs + rg * 32 + 4 * q);
            acc[4 * q] = b4.x; acc[4 * q + 1] = b4.y;
            acc[4 * q + 2] = b4.z; acc[4 * q + 3] = b4.w;
        }
        const float* wp = Wt + rg * 64 * 32;
#pragma unroll 8
        for (int k = 0; k < 64; ++k) {
            float xm = mp[k];
            const float* w = wp + k * 32;
#pragma unroll
            for (int q = 0; q < 8; ++q) {
                float4 w4 = *(const float4*)(w + 4 * q);
                acc[4 * q]     = fmaf(xm, w4.x, acc[4 * q]);
                acc[4 * q + 1] = fmaf(xm, w4.y, acc[4 * q + 1]);
                acc[4 * q + 2] = fmaf(xm, w4.z, acc[4 * q + 2]);
                acc[4 * q + 3] = fmaf(xm, w4.w, acc[4 * q + 3]);
            }
        }
#pragma unroll
        for (int c = 0; c < 32; ++c) st[lane * 33 + c] = acc[c];
        __syncwarp();
#pragma unroll
        for (int r = 0; r < 8; ++r) {
            int v = 4 * r + (lane >> 3);
            int c = 4 * (lane & 7);
            if (v < nvalid) {
                float4 o = make_float4(st[v * 33 + c], st[v * 33 + c + 1],
                                       st[v * 33 + c + 2], st[v * 33 + c + 3]);
                *(float4*)(rb + (size_t)(tb + v) * 224 + rg * 32 + c) = o;
            }
        }
        __syncwarp();
    }
}

// ---------------- scatter + skip concat ----------------
__global__ __launch_bounds__(256) void k_scatter(const float* __restrict__ x2,
                                                 const int* __restrict__ top,
                                                 const int* __restrict__ down)
{
    int b = blockIdx.y;
    int v0 = blockIdx.x * 256;
    const float* fb = g_raw + (size_t)b * V1 * 224;
    float* yb = g_y + (size_t)b * V2 * 64;
    int tid = threadIdx.x;
    for (int pass = 0; pass < 8; ++pass) {
        int vl = pass * 32 + (tid >> 3);
        int v = v0 + vl;
        int c0 = 4 * (tid & 7);
        if (v < V1) {
            int t = top[v];
            float4 f = *(const float4*)(fb + (size_t)t * 32 + c0);
            *(float4*)(yb + (size_t)v * 64 + c0) = f;
        } else if (v < V2) {
            int n = v - V1;
            int r = down[2 * n + (c0 >= 16 ? 1 : 0)];
            int base = (2 * c0) & 31;
            float4 f0 = *(const float4*)(fb + (size_t)r * 32 + base);
            float4 f1 = *(const float4*)(fb + (size_t)r * 32 + base + 4);
            float4 o;
            o.x = 0.5f * (f0.x + f0.y); o.y = 0.5f * (f0.z + f0.w);
            o.z = 0.5f * (f1.x + f1.y); o.w = 0.5f * (f1.z + f1.w);
            *(float4*)(yb + (size_t)v * 64 + c0) = o;
        }
    }
    const float* x2b = x2 + (size_t)b * 32 * V2;
    for (int i = tid; i < 256 * 32; i += 256) {
        int c = i & 31, vl = i >> 5;
        int v = v0 + vl;
        if (v < V2) yb[(size_t)v * 64 + 32 + c] = x2b[(size_t)c * V2 + v];
    }
}

// ---------------- conv1: double-buffered pipelined gather + GEMM + stats ----------------
__global__ __launch_bounds__(512) void k_conv1(const int* __restrict__ neigh,
                                               const float* __restrict__ b1)
{
    float* Wt = smem;                          // [448][32]
    float* mblk = Wt + 448 * 32;               // 16 x [2][32][33]
    int* nblk = (int*)(mblk + 16 * 2112);      // 16 x [7][32]
    int tid = threadIdx.x, b = blockIdx.y;
    for (int i = tid; i < 448 * 32; i += 512) Wt[i] = g_W1t[i];
    __syncthreads();

    int warp = tid >> 5, lane = tid & 31;
    int tb = (blockIdx.x * 16 + warp) * 32;
    if (tb >= V2) return;
    int nvalid = V2 - tb; if (nvalid > 32) nvalid = 32;
    float* mw = mblk + warp * 2112;
    int* nidxT = nblk + warp * 224;
    const float* yb = g_y + (size_t)b * V2 * 64;
    float* hb = g_h1 + (size_t)b * V2 * 32;

    {
        int vv = tb + (lane < nvalid ? lane : 0);
#pragma unroll
        for (int q = 0; q < 7; ++q)
            nidxT[q * 32 + lane] = neigh[(size_t)vv * 7 + q];
    }
    __syncwarp();

    float acc[32];
#pragma unroll
    for (int q = 0; q < 8; ++q) {
        float4 b4 = *(const float4*)(b1 + 4 * q);
        acc[4 * q] = b4.x; acc[4 * q + 1] = b4.y;
        acc[4 * q + 2] = b4.z; acc[4 * q + 3] = b4.w;
    }

    int rsel = lane >> 3;
    int cg = 4 * (lane & 7);
    const float* mp0 = mw + lane * 33;
    float4 pf[8];

    // prologue: gather chunk0 -> buf0, start gather chunk1
#pragma unroll
    for (int r = 0; r < 8; ++r) {
        int nb = nidxT[0 * 32 + 4 * r + rsel];
        pf[r] = *(const float4*)(yb + (size_t)nb * 64 + cg);
    }
#pragma unroll
    for (int r = 0; r < 8; ++r) {
        int v = 4 * r + rsel;
        float* d = mw + v * 33 + cg;
        d[0] = pf[r].x; d[1] = pf[r].y; d[2] = pf[r].z; d[3] = pf[r].w;
    }
    {
        int j = 0, bc = 32 + cg;   // chunk1 = (j=0, hi half)
#pragma unroll
        for (int r = 0; r < 8; ++r) {
            int nb = nidxT[j * 32 + 4 * r + rsel];
            pf[r] = *(const float4*)(yb + (size_t)nb * 64 + bc);
        }
    }
    __syncwarp();

    for (int ch = 0; ch < 14; ++ch) {
        const float* mp = mp0 + (ch & 1) * 1056;
        const float* wp = Wt + ch * 32 * 32;
#pragma unroll 8
        for (int kk = 0; kk < 32; ++kk) {
            float xm = mp[kk];
            const float* w = wp + kk * 32;
#pragma unroll
            for (int q = 0; q < 8; ++q) {
                float4 w4 = *(const float4*)(w + 4 * q);
                acc[4 * q]     = fmaf(xm, w4.x, acc[4 * q]);
                acc[4 * q + 1] = fmaf(xm, w4.y, acc[4 * q + 1]);
                acc[4 * q + 2] = fmaf(xm, w4.z, acc[4 * q + 2]);
                acc[4 * q + 3] = fmaf(xm, w4.w, acc[4 * q + 3]);
            }
        }
        if (ch < 13) {
            // store prefetched chunk ch+1 into the other buffer
            float* dbuf = mw + ((ch + 1) & 1) * 1056;
#pragma unroll
            for (int r = 0; r < 8; ++r) {
                int v = 4 * r + rsel;
                float* d = dbuf + v * 33 + cg;
                d[0] = pf[r].x; d[1] = pf[r].y; d[2] = pf[r].z; d[3] = pf[r].w;
            }
            if (ch < 12) {
                int nc = ch + 2;
                int j = nc >> 1;
                int bc = ((nc & 1) << 5) + cg;
#pragma unroll
                for (int r = 0; r < 8; ++r) {
                    int nb = nidxT[j * 32 + 4 * r + rsel];
                    pf[r] = *(const float4*)(yb + (size_t)nb * 64 + bc);
                }
            }
            __syncwarp();
        }
    }
    __syncwarp();

    if (lane >= nvalid) {
#pragma unroll
        for (int c = 0; c < 32; ++c) acc[c] = 0.f;
    }
    float* st = mw;
#pragma unroll
    for (int c = 0; c < 32; ++c) st[lane * 33 + c] = acc[c];
    __syncwarp();
#pragma unroll
    for (int r = 0; r < 8; ++r) {
        int v = 4 * r + rsel;
        if (v < nvalid) {
            float4 o = make_float4(st[v * 33 + cg], st[v * 33 + cg + 1],
                                   st[v * 33 + cg + 2], st[v * 33 + cg + 3]);
            *(float4*)(hb + (size_t)(tb + v) * 32 + cg) = o;
        }
    }
    float s = 0.f, q = 0.f;
#pragma unroll 8
    for (int v = 0; v < 32; ++v) {
        float x = st[v * 33 + lane];
        s += x;
        q = fmaf(x, x, q);
    }
    atomicAdd(&g_s1[b * 32 + lane], s);
    atomicAdd(&g_q1[b * 32 + lane], q);
}

// ---------------- BN finalize ----------------
__global__ void k_bnfin(int which, const float* __restrict__ g, const float* __restrict__ be)
{
    int i = threadIdx.x;
    if (i >= NB * 32) return;
    int c = i & 31;
    float s = which ? g_s2[i] : g_s1[i];
    float q = which ? g_q2[i] : g_q1[i];
    float mean = s / (float)V2;
    float var = q / (float)V2 - mean * mean;
    float scale = g[c] * rsqrtf(var + EPSF);
    float shift = be[c] - mean * scale;
    if (which) { g_sc2[i] = scale; g_sh2[i] = shift; }
    else       { g_sc1[i] = scale; g_sh1[i] = shift; }
}

// ---------------- conv2: double-buffered, BN1+LReLU folded ----------------
__global__ __launch_bounds__(512) void k_conv2(const int* __restrict__ neigh,
                                               const float* __restrict__ b2)
{
    float* Wt = smem;                          // [224][32]
    float* mblk = Wt + 224 * 32;               // 16 x [2][32][33]
    int* nblk = (int*)(mblk + 16 * 2112);      // 16 x [7][32]
    int tid = threadIdx.x, b = blockIdx.y;
    for (int i = tid; i < 224 * 32; i += 512) Wt[i] = g_W2t[i];
    __syncthreads();

    int warp = tid >> 5, lane = tid & 31;
    int tb = (blockIdx.x * 16 + warp) * 32;
    if (tb >= V2) return;
    int nvalid = V2 - tb; if (nvalid > 32) nvalid = 32;
    float* mw = mblk + warp * 2112;
    int* nidxT = nblk + warp * 224;
    const float* h1b = g_h1 + (size_t)b * V2 * 32;
    float* h2b = g_h2 + (size_t)b * V2 * 32;

    {
        int vv = tb + (lane < nvalid ? lane : 0);
#pragma unroll
        for (int q = 0; q < 7; ++q)
            nidxT[q * 32 + lane] = neigh[(size_t)vv * 7 + q];
    }
    __syncwarp();

    int rsel = lane >> 3;
    int cg = 4 * (lane & 7);
    float4 sc4 = *(const float4*)(g_sc1 + b * 32 + cg);
    float4 sh4 = *(const float4*)(g_sh1 + b * 32 + cg);

    float acc[32];
#pragma unroll
    for (int q = 0; q < 8; ++q) {
        float4 b4 = *(const float4*)(b2 + 4 * q);
        acc[4 * q] = b4.x; acc[4 * q + 1] = b4.y;
        acc[4 * q + 2] = b4.z; acc[4 * q + 3] = b4.w;
    }

    const float* mp0 = mw + lane * 33;
    float4 pf[8];

#pragma unroll
    for (int r = 0; r < 8; ++r) {
        int nb = nidxT[0 * 32 + 4 * r + rsel];
        pf[r] = *(const float4*)(h1b + (size_t)nb * 32 + cg);
    }
    // STS chunk0 (with BN fold)
#pragma unroll
    for (int r = 0; r < 8; ++r) {
        int v = 4 * r + rsel;
        float4 f = pf[r];
        f.x = fmaf(f.x, sc4.x, sh4.x); f.x = f.x >= 0.f ? f.x : SLOPE * f.x;
        f.y = fmaf(f.y, sc4.y, sh4.y); f.y = f.y >= 0.f ? f.y : SLOPE * f.y;
        f.z = fmaf(f.z, sc4.z, sh4.z); f.z = f.z >= 0.f ? f.z : SLOPE * f.z;
        f.w = fmaf(f.w, sc4.w, sh4.w); f.w = f.w >= 0.f ? f.w : SLOPE * f.w;
        float* d = mw + v * 33 + cg;
        d[0] = f.x; d[1] = f.y; d[2] = f.z; d[3] = f.w;
    }
#pragma unroll
    for (int r = 0; r < 8; ++r) {
        int nb = nidxT[1 * 32 + 4 * r + rsel];
        pf[r] = *(const float4*)(h1b + (size_t)nb * 32 + cg);
    }
    __syncwarp();

    for (int ch = 0; ch < 7; ++ch) {
        const float* mp = mp0 + (ch & 1) * 1056;
        const float* wp = Wt + ch * 32 * 32;
#pragma unroll 8
        for (int kk = 0; kk < 32; ++kk) {
            float xm = mp[kk];
            const float* w = wp + kk * 32;
#pragma unroll
            for (int q = 0; q < 8; ++q) {
                float4 w4 = *(const float4*)(w + 4 * q);
                acc[4 * q]     = fmaf(xm, w4.x, acc[4 * q]);
                acc[4 * q + 1] = fmaf(xm, w4.y, acc[4 * q + 1]);
                acc[4 * q + 2] = fmaf(xm, w4.z, acc[4 * q + 2]);
                acc[4 * q + 3] = fmaf(xm, w4.w, acc[4 * q + 3]);
            }
        }
        if (ch < 6) {
            float* dbuf = mw + ((ch + 1) & 1) * 1056;
#pragma unroll
            for (int r = 0; r < 8; ++r) {
                int v = 4 * r + rsel;
                float4 f = pf[r];
                f.x = fmaf(f.x, sc4.x, sh4.x); f.x = f.x >= 0.f ? f.x : SLOPE * f.x;
                f.y = fmaf(f.y, sc4.y, sh4.y); f.y = f.y >= 0.f ? f.y : SLOPE * f.y;
                f.z = fmaf(f.z, sc4.z, sh4.z); f.z = f.z >= 0.f ? f.z : SLOPE * f.z;
                f.w = fmaf(f.w, sc4.w, sh4.w); f.w = f.w >= 0.f ? f.w : SLOPE * f.w;
                float* d = dbuf + v * 33 + cg;
                d[0] = f.x; d[1] = f.y; d[2] = f.z; d[3] = f.w;
            }
            if (ch < 5) {
                int j = ch + 2;
#pragma unroll
                for (int r = 0; r < 8; ++r) {
                    int nb = nidxT[j * 32 + 4 * r + rsel];
                    pf[r] = *(const float4*)(h1b + (size_t)nb * 32 + cg);
                }
            }
            __syncwarp();
        }
    }
    __syncwarp();

    if (lane >= nvalid) {
#pragma unroll
        for (int c = 0; c < 32; ++c) acc[c] = 0.f;
    }
    float* st = mw;
#pragma unroll
    for (int c = 0; c < 32; ++c) st[lane * 33 + c] = acc[c];
    __syncwarp();
#pragma unroll
    for (int r = 0; r < 8; ++r) {
        int v = 4 * r + rsel;
        if (v < nvalid) {
            float4 o = make_float4(st[v * 33 + cg], st[v * 33 + cg + 1],
                                   st[v * 33 + cg + 2], st[v * 33 + cg + 3]);
            *(float4*)(h2b + (size_t)(tb + v) * 32 + cg) = o;
        }
    }
    float s = 0.f, q = 0.f;
#pragma unroll 8
    for (int v = 0; v < 32; ++v) {
        float x = st[v * 33 + lane];
        s += x;
        q = fmaf(x, x, q);
    }
    atomicAdd(&g_s2[b * 32 + lane], s);
    atomicAdd(&g_q2[b * 32 + lane], q);
}

// ---------------- BN2 + LReLU + transpose out ----------------
__global__ __launch_bounds__(256) void k_final(float* __restrict__ out)
{
    __shared__ float tile[32 * 33];
    int b = blockIdx.y, v0 = blockIdx.x * 32;
    const float* hb = g_h2 + (size_t)b * V2 * 32;
    int tid = threadIdx.x;
    for (int i = tid; i < 1024; i += 256) {
        int c = i & 31, vi = i >> 5;
        int v = v0 + vi;
        tile[vi * 33 + c] = (v < V2) ? hb[(size_t)v * 32 + c] : 0.f;
    }
    __syncthreads();
    for (int i = tid; i < 1024; i += 256) {
        int vi = i & 31, c = i >> 5;
        int v = v0 + vi;
        if (v < V2) {
            float y = fmaf(tile[vi * 33 + c], g_sc2[b * 32 + c], g_sh2[b * 32 + c]);
            out[((size_t)b * 32 + c) * V2 + v] = (y >= 0.f) ? y : SLOPE * y;
        }
    }
}

// ---------------- launch ----------------
extern "C" void kernel_launch(void* const* d_in, const int* in_sizes, int n_in,
                              void* d_out, int out_size)
{
    const float* x1   = (const float*)d_in[0];
    const float* x2   = (const float*)d_in[1];
    const int* neigh  = (const int*)d_in[2];
    const int* top    = (const int*)d_in[3];
    const int* down   = (const int*)d_in[4];
    const float* W_up = (const float*)d_in[5];
    const float* b_up = (const float*)d_in[6];
    const float* W1   = (const float*)d_in[7];
    const float* b1   = (const float*)d_in[8];
    const float* g1   = (const float*)d_in[9];
    const float* be1  = (const float*)d_in[10];
    const float* W2   = (const float*)d_in[11];
    const float* b2   = (const float*)d_in[12];
    const float* g2   = (const float*)d_in[13];
    const float* be2  = (const float*)d_in[14];
    float* out = (float*)d_out;

    const size_t ug_smem = (size_t)(7 * 64 * 32 + 224 + 8 * 32 * 65 + 8 * 32 * 33) * 4;
    const size_t c1_smem = (size_t)(448 * 32 + 16 * 2112 + 16 * 224) * 4;
    const size_t c2_smem = (size_t)(224 * 32 + 16 * 2112 + 16 * 224) * 4;
    cudaFuncSetAttribute(k_upgemm, cudaFuncAttributeMaxDynamicSharedMemorySize, (int)ug_smem);
    cudaFuncSetAttribute(k_conv1, cudaFuncAttributeMaxDynamicSharedMemorySize, (int)c1_smem);
    cudaFuncSetAttribute(k_conv2, cudaFuncAttributeMaxDynamicSharedMemorySize, (int)c2_smem);

    k_prep<<<32, 256>>>(W1, W2, W_up);

    int ug_tiles = (V1 + 31) / 32;
    dim3 gug((ug_tiles + 7) / 8, NB);
    k_upgemm<<<gug, 256, ug_smem>>>(x1, b_up);

    dim3 gsc((V2 + 255) / 256, NB);
    k_scatter<<<gsc, 256>>>(x2, top, down);

    int cv_tiles = (V2 + 31) / 32;   // 5121
    dim3 gcv((cv_tiles + 15) / 16, NB);
    k_conv1<<<gcv, 512, c1_smem>>>(neigh, b1);

    k_bnfin<<<1, 128>>>(0, g1, be1);

    k_conv2<<<gcv, 512, c2_smem>>>(neigh, b2);

    k_bnfin<<<1, 128>>>(1, g2, be2);

    dim3 gfin((V2 + 31) / 32, NB);
    k_final<<<gfin, 256>>>(out);
}